// round 6
// baseline (speedup 1.0000x reference)
#include <cuda_runtime.h>
#include <cuda_bf16.h>
#include <cstdint>
#include <cstddef>

// ---------------------------------------------------------------------------
// Problem constants
// ---------------------------------------------------------------------------
#define BTOT   4096
#define NTOK   49
#define CDIM   384
#define HEADS  12
#define HDIM   32
#define MROWS  (BTOT * NTOK)        // 200704
#define KDIM   384
#define N_QKV  1152

// Scratch (__device__ globals: the allowed alloc-free pattern)
__device__ float g_qkv[(size_t)MROWS * N_QKV];   // ~925 MB
__device__ float g_ctx[(size_t)MROWS * CDIM];    // ~308 MB (tf32-rounded by attn)
__device__ float g_wq [(size_t)KDIM * N_QKV];    // W_qkv rounded (row-major K x N)
__device__ float g_wp [(size_t)KDIM * CDIM];     // W_proj rounded
__device__ float g_bias[(size_t)HEADS * NTOK * NTOK];  // bias[h][i*49+j]

// ---------------------------------------------------------------------------
// Helpers
// ---------------------------------------------------------------------------
__device__ __forceinline__ float tf32r(float x) {
    uint32_t u;
    asm("cvt.rna.tf32.f32 %0, %1;" : "=r"(u) : "f"(x));
    return __uint_as_float(u);
}
__device__ __forceinline__ uint32_t fautf(float x) {   // round + reinterpret
    uint32_t u;
    asm("cvt.rna.tf32.f32 %0, %1;" : "=r"(u) : "f"(x));
    return u;
}
__device__ __forceinline__ uint32_t fau(float x) { return __float_as_uint(x); }

__device__ __forceinline__ uint32_t smem_u32(const void* p) {
    return (uint32_t)__cvta_generic_to_shared(p);
}
__device__ __forceinline__ void cp16(uint32_t dst, const void* src) {
    asm volatile("cp.async.cg.shared.global [%0], [%1], 16;" :: "r"(dst), "l"(src));
}
__device__ __forceinline__ void cp_commit() {
    asm volatile("cp.async.commit_group;" ::: "memory");
}
__device__ __forceinline__ void cp_wait1() {
    asm volatile("cp.async.wait_group 1;" ::: "memory");
}

__device__ __forceinline__ void mma_tf32(float c[4], const uint32_t a[4], const uint32_t b[2]) {
    asm volatile(
        "mma.sync.aligned.m16n8k8.row.col.f32.tf32.tf32.f32 "
        "{%0,%1,%2,%3}, {%4,%5,%6,%7}, {%8,%9}, {%0,%1,%2,%3};"
        : "+f"(c[0]), "+f"(c[1]), "+f"(c[2]), "+f"(c[3])
        : "r"(a[0]), "r"(a[1]), "r"(a[2]), "r"(a[3]), "r"(b[0]), "r"(b[1]));
}

// ---------------------------------------------------------------------------
// Prep kernels
// ---------------------------------------------------------------------------
__global__ void round_tf32_kernel(const float4* __restrict__ in,
                                  float4* __restrict__ out, int n4)
{
    for (int i = blockIdx.x * blockDim.x + threadIdx.x; i < n4;
         i += gridDim.x * blockDim.x) {
        float4 v = in[i];
        v.x = tf32r(v.x); v.y = tf32r(v.y); v.z = tf32r(v.z); v.w = tf32r(v.w);
        out[i] = v;
    }
}

// bias_g[h][i*49+j] = table[relix[i*49+j]*HEADS + h]
__global__ void bias_build_kernel(const float* __restrict__ table,
                                  const int* __restrict__ relix,
                                  float* __restrict__ bias_g)
{
    int idx = blockIdx.x * blockDim.x + threadIdx.x;
    if (idx < HEADS * NTOK * NTOK) {
        int h = idx / (NTOK * NTOK), ij = idx % (NTOK * NTOK);
        bias_g[idx] = table[relix[ij] * HEADS + h];
    }
}

// ---------------------------------------------------------------------------
// GEMM: C[M x Ncols] = A[M x 384] @ B[384 x Ncols] + bias
// (unchanged from round 5 — validated)
// ---------------------------------------------------------------------------
#define AS_STRIDE 36
#define BS_STRIDE 132
#define AS_BYTES  (128 * AS_STRIDE * 4)   // 18432
#define BS_BYTES  (32 * BS_STRIDE * 4)    // 16896
#define STG_BYTES (AS_BYTES + BS_BYTES)   // 35328
#define GEMM_SMEM (2 * STG_BYTES)         // 70656

__global__ void __launch_bounds__(128, 3)
gemm_tf32_kernel(const float* __restrict__ A, const float* __restrict__ B,
                 const float* __restrict__ bias, float* __restrict__ C, int Ncols)
{
    extern __shared__ char smem[];
    const uint32_t sb = smem_u32(smem);

    const int tid  = threadIdx.x;
    const int warp = tid >> 5, lane = tid & 31;
    const int wm   = warp >> 1, wn = warp & 1;
    const int g    = lane >> 2, t = lane & 3;
    const int m0   = blockIdx.y * 128;
    const int n0   = blockIdx.x * 128;

    float acc[4][8][4];
    #pragma unroll
    for (int mi = 0; mi < 4; mi++)
        #pragma unroll
        for (int nj = 0; nj < 8; nj++)
            #pragma unroll
            for (int r = 0; r < 4; r++) acc[mi][nj][r] = 0.f;

    const char* gA = (const char*)(A + (size_t)m0 * KDIM);
    const char* gB = (const char*)B;

    auto load_stage = [&](int kt, int s) {
        const uint32_t sA = sb + s * STG_BYTES;
        const uint32_t sB = sA + AS_BYTES;
        const size_t kbA = (size_t)kt * 128;
        #pragma unroll
        for (int j = 0; j < 8; j++) {
            int c = tid + j * 128;
            int row = c >> 3, cic = c & 7;
            cp16(sA + row * (AS_STRIDE * 4) + cic * 16,
                 gA + (size_t)row * (KDIM * 4) + kbA + cic * 16);
        }
        #pragma unroll
        for (int j = 0; j < 8; j++) {
            int c = tid + j * 128;
            int row = c >> 5, cic = c & 31;
            cp16(sB + row * (BS_STRIDE * 4) + cic * 16,
                 gB + (size_t)(kt * 32 + row) * ((size_t)Ncols * 4)
                    + (size_t)n0 * 4 + cic * 16);
        }
    };

    auto compute = [&](int s) {
        const float* as = (const float*)(smem + s * STG_BYTES);
        const float* bs = (const float*)(smem + s * STG_BYTES + AS_BYTES);
        #pragma unroll
        for (int kk = 0; kk < 4; kk++) {
            uint32_t afr[4][4], bfr[8][2];
            #pragma unroll
            for (int mi = 0; mi < 4; mi++) {
                int mb = wm * 64 + mi * 16;
                afr[mi][0] = fautf(as[(mb + g)     * AS_STRIDE + kk * 8 + t]);
                afr[mi][1] = fautf(as[(mb + g + 8) * AS_STRIDE + kk * 8 + t]);
                afr[mi][2] = fautf(as[(mb + g)     * AS_STRIDE + kk * 8 + t + 4]);
                afr[mi][3] = fautf(as[(mb + g + 8) * AS_STRIDE + kk * 8 + t + 4]);
            }
            #pragma unroll
            for (int nj = 0; nj < 8; nj++) {
                int nb = wn * 64 + nj * 8;
                bfr[nj][0] = fau(bs[(kk * 8 + t)     * BS_STRIDE + nb + g]);
                bfr[nj][1] = fau(bs[(kk * 8 + t + 4) * BS_STRIDE + nb + g]);
            }
            #pragma unroll
            for (int mi = 0; mi < 4; mi++)
                #pragma unroll
                for (int nj = 0; nj < 8; nj++)
                    mma_tf32(acc[mi][nj], afr[mi], bfr[nj]);
        }
    };

    load_stage(0, 0); cp_commit();
    load_stage(1, 1); cp_commit();

    #pragma unroll 1
    for (int kt = 0; kt < 12; kt++) {
        int s = kt & 1;
        cp_wait1();
        __syncthreads();
        compute(s);
        __syncthreads();
        if (kt + 2 < 12) load_stage(kt + 2, s);
        cp_commit();
    }

    #pragma unroll
    for (int mi = 0; mi < 4; mi++) {
        #pragma unroll
        for (int nj = 0; nj < 8; nj++) {
            int row = m0 + wm * 64 + mi * 16 + g;
            int col = n0 + wn * 64 + nj * 8 + 2 * t;
            float2 bb = *(const float2*)(bias + col);
            float2 v0 = make_float2(acc[mi][nj][0] + bb.x, acc[mi][nj][1] + bb.y);
            float2 v1 = make_float2(acc[mi][nj][2] + bb.x, acc[mi][nj][3] + bb.y);
            *(float2*)(C + (size_t)row * Ncols + col)       = v0;
            *(float2*)(C + (size_t)(row + 8) * Ncols + col) = v1;
        }
    }
}

// ---------------------------------------------------------------------------
// Tensor-core attention. Block = (window, head-pair): 128 threads, 4 warps.
// Warp (hh, mwarp): head hh, M-rows [mwarp*32, mwarp*32+32) of the padded 64.
// S = QK^T via mma (K row-major [j][d]); softmax fully in registers
// (row lives in a 4-lane t-group -> shfl_xor 1,2); P->A-fragment via shuffles;
// O = P V via mma. No S/P smem. Padded cols forced to -1e30 -> P=0 exactly.
// ---------------------------------------------------------------------------
#define HQS 36     // q/k smem row stride (floats): frag banks 4g+t, CF
#define HVS 40     // v smem row stride: frag banks 8t+g, CF

__global__ void __launch_bounds__(128, 3)
attn_tc_kernel(const float* __restrict__ qkv, const float* __restrict__ bias_g,
               float* __restrict__ ctx)
{
    __shared__ __align__(16) float q_s[2][NTOK * HQS];
    __shared__ __align__(16) float k_s[2][NTOK * HQS];
    __shared__ __align__(16) float v_s[2][56 * HVS];

    const int w  = blockIdx.x;
    const int hp = blockIdx.y;              // head pair 0..5
    const int tid = threadIdx.x, wid = tid >> 5, lane = tid & 31;
    const int hh = wid >> 1, mwarp = wid & 1;
    const int h  = hp * 2 + hh;
    const int g  = lane >> 2, t = lane & 3;
    const float scale = 0.1767766952966369f;   // 32^-0.5

    // ---- load q,k,v for both heads of the pair ----
    #pragma unroll
    for (int hl = 0; hl < 2; hl++) {
        const float* base = qkv + (size_t)w * NTOK * N_QKV + (size_t)(hp * 2 + hl) * HDIM;
        for (int idx = tid; idx < 3 * 392; idx += 128) {
            int mat = idx / 392;                 // 0=q 1=k 2=v
            int rem = idx - mat * 392;
            int r = rem >> 3, d4 = (rem & 7) * 4;
            float4 vv = *(const float4*)(base + (size_t)r * N_QKV + mat * CDIM + d4);
            if (mat == 0) {
                vv.x *= scale; vv.y *= scale; vv.z *= scale; vv.w *= scale;
                *(float4*)&q_s[hl][r * HQS + d4] = vv;
            } else if (mat == 1) {
                *(float4*)&k_s[hl][r * HQS + d4] = vv;
            } else {
                *(float4*)&v_s[hl][r * HVS + d4] = vv;
            }
        }
        // zero-pad V rows 49..55 (k-dim padding for the O mma)
        for (int idx = tid; idx < 70; idx += 128) {
            int r = NTOK + idx / 10, c4 = (idx % 10) * 4;
            *(float4*)&v_s[hl][r * HVS + c4] = make_float4(0.f, 0.f, 0.f, 0.f);
        }
    }
    __syncthreads();

    const float* Q = q_s[hh];
    const float* K = k_s[hh];
    const float* V = v_s[hh];

    // ---- S = Q K^T (2 m-tiles x 7 n-tiles, k = 32 in 4 steps) ----
    float sacc[2][7][4];
    #pragma unroll
    for (int mi = 0; mi < 2; mi++)
        #pragma unroll
        for (int nj = 0; nj < 7; nj++)
            #pragma unroll
            for (int r = 0; r < 4; r++) sacc[mi][nj][r] = 0.f;

    #pragma unroll
    for (int kk = 0; kk < 4; kk++) {
        uint32_t afr[2][4];
        #pragma unroll
        for (int mi = 0; mi < 2; mi++) {
            int mb = mwarp * 32 + mi * 16;
            int r0 = mb + g, r1 = mb + g + 8;
            afr[mi][0] = (r0 < NTOK) ? fautf(Q[r0 * HQS + kk * 8 + t])     : 0u;
            afr[mi][1] = (r1 < NTOK) ? fautf(Q[r1 * HQS + kk * 8 + t])     : 0u;
            afr[mi][2] = (r0 < NTOK) ? fautf(Q[r0 * HQS + kk * 8 + t + 4]) : 0u;
            afr[mi][3] = (r1 < NTOK) ? fautf(Q[r1 * HQS + kk * 8 + t + 4]) : 0u;
        }
        #pragma unroll
        for (int nj = 0; nj < 7; nj++) {
            int col = nj * 8 + g;
            uint32_t bfr[2];
            bfr[0] = (col < NTOK) ? fautf(K[col * HQS + kk * 8 + t])     : 0u;
            bfr[1] = (col < NTOK) ? fautf(K[col * HQS + kk * 8 + t + 4]) : 0u;
            mma_tf32(sacc[0][nj], afr[0], bfr);
            mma_tf32(sacc[1][nj], afr[1], bfr);
        }
    }

    // ---- bias add + column guard ----
    const float* bh = bias_g + (size_t)h * (NTOK * NTOK);
    #pragma unroll
    for (int mi = 0; mi < 2; mi++) {
        int r0 = mwarp * 32 + mi * 16 + g;
        int r1 = r0 + 8;
        int br0 = min(r0, NTOK - 1) * NTOK;
        int br1 = min(r1, NTOK - 1) * NTOK;
        #pragma unroll
        for (int nj = 0; nj < 7; nj++) {
            int c0 = nj * 8 + 2 * t, c1 = c0 + 1;
            sacc[mi][nj][0] = (c0 < NTOK) ? sacc[mi][nj][0] + bh[br0 + c0] : -1e30f;
            sacc[mi][nj][1] = (c1 < NTOK) ? sacc[mi][nj][1] + bh[br0 + c1] : -1e30f;
            sacc[mi][nj][2] = (c0 < NTOK) ? sacc[mi][nj][2] + bh[br1 + c0] : -1e30f;
            sacc[mi][nj][3] = (c1 < NTOK) ? sacc[mi][nj][3] + bh[br1 + c1] : -1e30f;
        }
    }

    // ---- softmax in registers (rows live in 4-lane t-groups) ----
    #pragma unroll
    for (int mi = 0; mi < 2; mi++) {
        float m0 = -1e30f, m1 = -1e30f;
        #pragma unroll
        for (int nj = 0; nj < 7; nj++) {
            m0 = fmaxf(m0, fmaxf(sacc[mi][nj][0], sacc[mi][nj][1]));
            m1 = fmaxf(m1, fmaxf(sacc[mi][nj][2], sacc[mi][nj][3]));
        }
        m0 = fmaxf(m0, __shfl_xor_sync(0xffffffffu, m0, 1));
        m0 = fmaxf(m0, __shfl_xor_sync(0xffffffffu, m0, 2));
        m1 = fmaxf(m1, __shfl_xor_sync(0xffffffffu, m1, 1));
        m1 = fmaxf(m1, __shfl_xor_sync(0xffffffffu, m1, 2));
        float s0 = 0.f, s1 = 0.f;
        #pragma unroll
        for (int nj = 0; nj < 7; nj++) {
            sacc[mi][nj][0] = __expf(sacc[mi][nj][0] - m0); s0 += sacc[mi][nj][0];
            sacc[mi][nj][1] = __expf(sacc[mi][nj][1] - m0); s0 += sacc[mi][nj][1];
            sacc[mi][nj][2] = __expf(sacc[mi][nj][2] - m1); s1 += sacc[mi][nj][2];
            sacc[mi][nj][3] = __expf(sacc[mi][nj][3] - m1); s1 += sacc[mi][nj][3];
        }
        s0 += __shfl_xor_sync(0xffffffffu, s0, 1);
        s0 += __shfl_xor_sync(0xffffffffu, s0, 2);
        s1 += __shfl_xor_sync(0xffffffffu, s1, 1);
        s1 += __shfl_xor_sync(0xffffffffu, s1, 2);
        float i0 = 1.f / s0, i1 = 1.f / s1;
        #pragma unroll
        for (int nj = 0; nj < 7; nj++) {
            sacc[mi][nj][0] *= i0; sacc[mi][nj][1] *= i0;
            sacc[mi][nj][2] *= i1; sacc[mi][nj][3] *= i1;
        }
    }

    // ---- O = P V : P-fragments via t-group shuffles, V from smem ----
    float oacc[2][4][4];
    #pragma unroll
    for (int mi = 0; mi < 2; mi++)
        #pragma unroll
        for (int nd = 0; nd < 4; nd++)
            #pragma unroll
            for (int r = 0; r < 4; r++) oacc[mi][nd][r] = 0.f;

    const int src0 = (lane & ~3) | (t >> 1);       // col t       source lane
    const int src1 = src0 + 2;                     // col t+4     source lane
    const bool odd = (t & 1);

    #pragma unroll
    for (int jt = 0; jt < 7; jt++) {
        uint32_t pa[2][4];
        #pragma unroll
        for (int mi = 0; mi < 2; mi++) {
            float e, o;
            e = __shfl_sync(0xffffffffu, sacc[mi][jt][0], src0);
            o = __shfl_sync(0xffffffffu, sacc[mi][jt][1], src0);
            pa[mi][0] = fautf(odd ? o : e);
            e = __shfl_sync(0xffffffffu, sacc[mi][jt][2], src0);
            o = __shfl_sync(0xffffffffu, sacc[mi][jt][3], src0);
            pa[mi][1] = fautf(odd ? o : e);
            e = __shfl_sync(0xffffffffu, sacc[mi][jt][0], src1);
            o = __shfl_sync(0xffffffffu, sacc[mi][jt][1], src1);
            pa[mi][2] = fautf(odd ? o : e);
            e = __shfl_sync(0xffffffffu, sacc[mi][jt][2], src1);
            o = __shfl_sync(0xffffffffu, sacc[mi][jt][3], src1);
            pa[mi][3] = fautf(odd ? o : e);
        }
        uint32_t bfr[4][2];
        #pragma unroll
        for (int nd = 0; nd < 4; nd++) {
            bfr[nd][0] = fautf(V[(jt * 8 + t)     * HVS + nd * 8 + g]);
            bfr[nd][1] = fautf(V[(jt * 8 + t + 4) * HVS + nd * 8 + g]);
        }
        #pragma unroll
        for (int mi = 0; mi < 2; mi++)
            #pragma unroll
            for (int nd = 0; nd < 4; nd++)
                mma_tf32(oacc[mi][nd], pa[mi], bfr[nd]);
    }

    // ---- store O (tf32-rounded: feeds the proj GEMM) ----
    #pragma unroll
    for (int mi = 0; mi < 2; mi++) {
        int r0 = mwarp * 32 + mi * 16 + g;
        int r1 = r0 + 8;
        #pragma unroll
        for (int nd = 0; nd < 4; nd++) {
            int d0 = nd * 8 + 2 * t;
            if (r0 < NTOK) {
                float2 v0 = make_float2(tf32r(oacc[mi][nd][0]), tf32r(oacc[mi][nd][1]));
                *(float2*)(ctx + ((size_t)w * NTOK + r0) * CDIM + h * HDIM + d0) = v0;
            }
            if (r1 < NTOK) {
                float2 v1 = make_float2(tf32r(oacc[mi][nd][2]), tf32r(oacc[mi][nd][3]));
                *(float2*)(ctx + ((size_t)w * NTOK + r1) * CDIM + h * HDIM + d0) = v1;
            }
        }
    }
}

// ---------------------------------------------------------------------------
// Launch
// ---------------------------------------------------------------------------
extern "C" void kernel_launch(void* const* d_in, const int* in_sizes, int n_in,
                              void* d_out, int out_size)
{
    const float* x     = (const float*)d_in[0];
    const float* Wqkv  = (const float*)d_in[1];
    const float* bqkv  = (const float*)d_in[2];
    const float* Wproj = (const float*)d_in[3];
    const float* bproj = (const float*)d_in[4];
    const float* table = (const float*)d_in[5];
    const int*   relix = (const int*)d_in[6];
    float* out = (float*)d_out;

    float *qkv, *ctx, *wq, *wp, *bias_g;
    cudaGetSymbolAddress((void**)&qkv, g_qkv);
    cudaGetSymbolAddress((void**)&ctx, g_ctx);
    cudaGetSymbolAddress((void**)&wq,  g_wq);
    cudaGetSymbolAddress((void**)&wp,  g_wp);
    cudaGetSymbolAddress((void**)&bias_g, g_bias);

    cudaFuncSetAttribute(gemm_tf32_kernel,
                         cudaFuncAttributeMaxDynamicSharedMemorySize, GEMM_SMEM);

    // 0) prep: round weights, build per-head bias table
    round_tf32_kernel<<<432, 256>>>((const float4*)Wqkv, (float4*)wq,
                                    (KDIM * N_QKV) / 4);
    round_tf32_kernel<<<144, 256>>>((const float4*)Wproj, (float4*)wp,
                                    (KDIM * CDIM) / 4);
    bias_build_kernel<<<(HEADS * NTOK * NTOK + 255) / 256, 256>>>(
        table, relix, bias_g);

    // 1) qkv = x @ W_qkv + b     (M=200704, N=1152, K=384)
    gemm_tf32_kernel<<<dim3(N_QKV / 128, MROWS / 128), 128, GEMM_SMEM>>>(
        x, wq, bqkv, qkv, N_QKV);

    // 2) attention (tensor-core), one block per (window, head-pair)
    attn_tc_kernel<<<dim3(BTOT, HEADS / 2), 128>>>(qkv, bias_g, ctx);

    // 3) out = ctx @ W_proj + b  (M=200704, N=384, K=384)
    gemm_tf32_kernel<<<dim3(CDIM / 128, MROWS / 128), 128, GEMM_SMEM>>>(
        ctx, wp, bproj, out, CDIM);
}

// round 7
// speedup vs baseline: 1.0516x; 1.0516x over previous
#include <cuda_runtime.h>
#include <cuda_bf16.h>
#include <cstdint>
#include <cstddef>

// ---------------------------------------------------------------------------
// Problem constants
// ---------------------------------------------------------------------------
#define BTOT   4096
#define NTOK   49
#define CDIM   384
#define HEADS  12
#define HDIM   32
#define MROWS  (BTOT * NTOK)        // 200704
#define KDIM   384
#define N_QKV  1152

// Scratch (__device__ globals: the allowed alloc-free pattern)
__device__ float g_qkv[(size_t)MROWS * N_QKV];   // ~925 MB (tf32-rounded)
__device__ float g_ctx[(size_t)MROWS * CDIM];    // ~308 MB
__device__ float g_wq [(size_t)KDIM * N_QKV];    // W_qkv rounded
__device__ float g_wp [(size_t)KDIM * CDIM];     // W_proj rounded
__device__ float g_bias[(size_t)HEADS * NTOK * NTOK];  // bias[h][i*49+j]

// ---------------------------------------------------------------------------
// Helpers
// ---------------------------------------------------------------------------
__device__ __forceinline__ float tf32r(float x) {
    uint32_t u;
    asm("cvt.rna.tf32.f32 %0, %1;" : "=r"(u) : "f"(x));
    return __uint_as_float(u);
}
__device__ __forceinline__ uint32_t fautf(float x) {   // round + reinterpret
    uint32_t u;
    asm("cvt.rna.tf32.f32 %0, %1;" : "=r"(u) : "f"(x));
    return u;
}
__device__ __forceinline__ uint32_t fau(float x) { return __float_as_uint(x); }

__device__ __forceinline__ uint32_t smem_u32(const void* p) {
    return (uint32_t)__cvta_generic_to_shared(p);
}
__device__ __forceinline__ void cp16(uint32_t dst, const void* src) {
    asm volatile("cp.async.cg.shared.global [%0], [%1], 16;" :: "r"(dst), "l"(src));
}
__device__ __forceinline__ void cp_commit() {
    asm volatile("cp.async.commit_group;" ::: "memory");
}
__device__ __forceinline__ void cp_wait1() {
    asm volatile("cp.async.wait_group 1;" ::: "memory");
}

__device__ __forceinline__ void mma_tf32(float c[4], const uint32_t a[4], const uint32_t b[2]) {
    asm volatile(
        "mma.sync.aligned.m16n8k8.row.col.f32.tf32.tf32.f32 "
        "{%0,%1,%2,%3}, {%4,%5,%6,%7}, {%8,%9}, {%0,%1,%2,%3};"
        : "+f"(c[0]), "+f"(c[1]), "+f"(c[2]), "+f"(c[3])
        : "r"(a[0]), "r"(a[1]), "r"(a[2]), "r"(a[3]), "r"(b[0]), "r"(b[1]));
}

// ---------------------------------------------------------------------------
// Prep kernels
// ---------------------------------------------------------------------------
__global__ void round_tf32_kernel(const float4* __restrict__ in,
                                  float4* __restrict__ out, int n4)
{
    for (int i = blockIdx.x * blockDim.x + threadIdx.x; i < n4;
         i += gridDim.x * blockDim.x) {
        float4 v = in[i];
        v.x = tf32r(v.x); v.y = tf32r(v.y); v.z = tf32r(v.z); v.w = tf32r(v.w);
        out[i] = v;
    }
}

__global__ void bias_build_kernel(const float* __restrict__ table,
                                  const int* __restrict__ relix,
                                  float* __restrict__ bias_g)
{
    int idx = blockIdx.x * blockDim.x + threadIdx.x;
    if (idx < HEADS * NTOK * NTOK) {
        int h = idx / (NTOK * NTOK), ij = idx % (NTOK * NTOK);
        bias_g[idx] = table[relix[ij] * HEADS + h];
    }
}

// ---------------------------------------------------------------------------
// GEMM: C[M x Ncols] = A[M x 384] @ B[384 x Ncols] + bias
// A: raw fp32 (tf32-rounded after LDS).  B: pre-rounded tf32.
// CTA 128x128, 256 threads = 8 warps (2x4), warp tile 64x32.
// BK=32, 2-stage cp.async pipeline; ~120 regs -> 2 CTAs/SM = 16 warps.
// round_out=true  -> store tf32-rounded (qkv feeding attention)
// ---------------------------------------------------------------------------
#define AS_STRIDE 36
#define BS_STRIDE 132
#define AS_BYTES  (128 * AS_STRIDE * 4)   // 18432
#define BS_BYTES  (32 * BS_STRIDE * 4)    // 16896
#define STG_BYTES (AS_BYTES + BS_BYTES)   // 35328
#define GEMM_SMEM (2 * STG_BYTES)         // 70656

__global__ void __launch_bounds__(256, 2)
gemm_tf32_kernel(const float* __restrict__ A, const float* __restrict__ B,
                 const float* __restrict__ bias, float* __restrict__ C,
                 int Ncols, int round_out)
{
    extern __shared__ char smem[];
    const uint32_t sb = smem_u32(smem);

    const int tid  = threadIdx.x;
    const int warp = tid >> 5, lane = tid & 31;
    const int wm   = warp >> 2, wn = warp & 3;       // 2 x 4 warp grid
    const int g    = lane >> 2, t = lane & 3;
    const int m0   = blockIdx.y * 128;
    const int n0   = blockIdx.x * 128;

    float acc[4][4][4];
    #pragma unroll
    for (int mi = 0; mi < 4; mi++)
        #pragma unroll
        for (int nj = 0; nj < 4; nj++)
            #pragma unroll
            for (int r = 0; r < 4; r++) acc[mi][nj][r] = 0.f;

    const char* gA = (const char*)(A + (size_t)m0 * KDIM);
    const char* gB = (const char*)B;

    auto load_stage = [&](int kt, int s) {
        const uint32_t sA = sb + s * STG_BYTES;
        const uint32_t sB = sA + AS_BYTES;
        const size_t kbA = (size_t)kt * 128;
        #pragma unroll
        for (int j = 0; j < 4; j++) {
            int c = tid + j * 256;                    // 0..1023
            int row = c >> 3, cic = c & 7;            // A: 128 rows x 8 chunks
            cp16(sA + row * (AS_STRIDE * 4) + cic * 16,
                 gA + (size_t)row * (KDIM * 4) + kbA + cic * 16);
        }
        #pragma unroll
        for (int j = 0; j < 4; j++) {
            int c = tid + j * 256;
            int row = c >> 5, cic = c & 31;           // B: 32 rows x 32 chunks
            cp16(sB + row * (BS_STRIDE * 4) + cic * 16,
                 gB + (size_t)(kt * 32 + row) * ((size_t)Ncols * 4)
                    + (size_t)n0 * 4 + cic * 16);
        }
    };

    auto compute = [&](int s) {
        const float* as = (const float*)(smem + s * STG_BYTES);
        const float* bs = (const float*)(smem + s * STG_BYTES + AS_BYTES);
        #pragma unroll
        for (int kk = 0; kk < 4; kk++) {
            uint32_t afr[4][4], bfr[4][2];
            #pragma unroll
            for (int mi = 0; mi < 4; mi++) {
                int mb = wm * 64 + mi * 16;
                afr[mi][0] = fautf(as[(mb + g)     * AS_STRIDE + kk * 8 + t]);
                afr[mi][1] = fautf(as[(mb + g + 8) * AS_STRIDE + kk * 8 + t]);
                afr[mi][2] = fautf(as[(mb + g)     * AS_STRIDE + kk * 8 + t + 4]);
                afr[mi][3] = fautf(as[(mb + g + 8) * AS_STRIDE + kk * 8 + t + 4]);
            }
            #pragma unroll
            for (int nj = 0; nj < 4; nj++) {
                int nb = wn * 32 + nj * 8;
                bfr[nj][0] = fau(bs[(kk * 8 + t)     * BS_STRIDE + nb + g]);
                bfr[nj][1] = fau(bs[(kk * 8 + t + 4) * BS_STRIDE + nb + g]);
            }
            #pragma unroll
            for (int mi = 0; mi < 4; mi++)
                #pragma unroll
                for (int nj = 0; nj < 4; nj++)
                    mma_tf32(acc[mi][nj], afr[mi], bfr[nj]);
        }
    };

    load_stage(0, 0); cp_commit();
    load_stage(1, 1); cp_commit();

    #pragma unroll 1
    for (int kt = 0; kt < 12; kt++) {
        int s = kt & 1;
        cp_wait1();
        __syncthreads();
        compute(s);
        __syncthreads();
        if (kt + 2 < 12) load_stage(kt + 2, s);
        cp_commit();
    }

    #pragma unroll
    for (int mi = 0; mi < 4; mi++) {
        #pragma unroll
        for (int nj = 0; nj < 4; nj++) {
            int row = m0 + wm * 64 + mi * 16 + g;
            int col = n0 + wn * 32 + nj * 8 + 2 * t;
            float2 bb = *(const float2*)(bias + col);
            float2 v0 = make_float2(acc[mi][nj][0] + bb.x, acc[mi][nj][1] + bb.y);
            float2 v1 = make_float2(acc[mi][nj][2] + bb.x, acc[mi][nj][3] + bb.y);
            if (round_out) {
                v0.x = tf32r(v0.x); v0.y = tf32r(v0.y);
                v1.x = tf32r(v1.x); v1.y = tf32r(v1.y);
            }
            *(float2*)(C + (size_t)row * Ncols + col)       = v0;
            *(float2*)(C + (size_t)(row + 8) * Ncols + col) = v1;
        }
    }
}

// ---------------------------------------------------------------------------
// Tensor-core attention. Block = (window, head-pair): 128 threads, 4 warps.
// qkv arrives tf32-pre-rounded -> fragment loads are plain reinterpret.
// q smem padded to 64 rows (zeros), k/v to 56 rows -> unguarded loads.
// Softmax in registers; P->A-fragment via t-group shuffles; O = P V via mma.
// ---------------------------------------------------------------------------
#define HQS 36
#define HVS 40

__global__ void __launch_bounds__(128, 3)
attn_tc_kernel(const float* __restrict__ qkv, const float* __restrict__ bias_g,
               float* __restrict__ ctx)
{
    __shared__ __align__(16) float q_s[2][64 * HQS];
    __shared__ __align__(16) float k_s[2][56 * HQS];
    __shared__ __align__(16) float v_s[2][56 * HVS];

    const int w  = blockIdx.x;
    const int hp = blockIdx.y;              // head pair 0..5
    const int tid = threadIdx.x, wid = tid >> 5, lane = tid & 31;
    const int hh = wid >> 1, mwarp = wid & 1;
    const int h  = hp * 2 + hh;
    const int g  = lane >> 2, t = lane & 3;
    const float scale = 0.1767766952966369f;   // 32^-0.5

    // ---- zero pads (disjoint from data fills; one sync at the end) ----
    #pragma unroll
    for (int hl = 0; hl < 2; hl++) {
        for (int i = tid; i < 15 * HQS; i += 128) q_s[hl][49 * HQS + i] = 0.f;
        for (int i = tid; i < 7 * HQS;  i += 128) k_s[hl][49 * HQS + i] = 0.f;
        for (int i = tid; i < 7 * HVS;  i += 128) v_s[hl][49 * HVS + i] = 0.f;
    }

    // ---- load q,k,v (qkv pre-rounded; re-round q after scaling) ----
    #pragma unroll
    for (int hl = 0; hl < 2; hl++) {
        const float* base = qkv + (size_t)w * NTOK * N_QKV + (size_t)(hp * 2 + hl) * HDIM;
        for (int idx = tid; idx < 392; idx += 128) {
            int r = idx >> 3, d4 = (idx & 7) * 4;
            float4 a = *(const float4*)(base + (size_t)r * N_QKV + d4);
            a.x = tf32r(a.x * scale); a.y = tf32r(a.y * scale);
            a.z = tf32r(a.z * scale); a.w = tf32r(a.w * scale);
            *(float4*)&q_s[hl][r * HQS + d4] = a;
            *(float4*)&k_s[hl][r * HQS + d4] =
                *(const float4*)(base + (size_t)r * N_QKV + CDIM + d4);
            *(float4*)&v_s[hl][r * HVS + d4] =
                *(const float4*)(base + (size_t)r * N_QKV + 2 * CDIM + d4);
        }
    }
    __syncthreads();

    const float* Q = q_s[hh];
    const float* K = k_s[hh];
    const float* V = v_s[hh];

    // ---- S = Q K^T (2 m-tiles x 7 n-tiles, k = 32 in 4 steps) ----
    float sacc[2][7][4];
    #pragma unroll
    for (int mi = 0; mi < 2; mi++)
        #pragma unroll
        for (int nj = 0; nj < 7; nj++)
            #pragma unroll
            for (int r = 0; r < 4; r++) sacc[mi][nj][r] = 0.f;

    #pragma unroll
    for (int kk = 0; kk < 4; kk++) {
        uint32_t afr[2][4];
        #pragma unroll
        for (int mi = 0; mi < 2; mi++) {
            int mb = mwarp * 32 + mi * 16;
            afr[mi][0] = fau(Q[(mb + g)     * HQS + kk * 8 + t]);
            afr[mi][1] = fau(Q[(mb + g + 8) * HQS + kk * 8 + t]);
            afr[mi][2] = fau(Q[(mb + g)     * HQS + kk * 8 + t + 4]);
            afr[mi][3] = fau(Q[(mb + g + 8) * HQS + kk * 8 + t + 4]);
        }
        #pragma unroll
        for (int nj = 0; nj < 7; nj++) {
            int col = nj * 8 + g;
            uint32_t bfr[2];
            bfr[0] = fau(K[col * HQS + kk * 8 + t]);
            bfr[1] = fau(K[col * HQS + kk * 8 + t + 4]);
            mma_tf32(sacc[0][nj], afr[0], bfr);
            mma_tf32(sacc[1][nj], afr[1], bfr);
        }
    }

    // ---- bias add + column guard (cols >= 49 -> -1e30 so P = 0) ----
    const float* bh = bias_g + (size_t)h * (NTOK * NTOK);
    #pragma unroll
    for (int mi = 0; mi < 2; mi++) {
        int r0 = mwarp * 32 + mi * 16 + g;
        int r1 = r0 + 8;
        int br0 = min(r0, NTOK - 1) * NTOK;
        int br1 = min(r1, NTOK - 1) * NTOK;
        #pragma unroll
        for (int nj = 0; nj < 7; nj++) {
            int c0 = nj * 8 + 2 * t, c1 = c0 + 1;
            sacc[mi][nj][0] = (c0 < NTOK) ? sacc[mi][nj][0] + bh[br0 + c0] : -1e30f;
            sacc[mi][nj][1] = (c1 < NTOK) ? sacc[mi][nj][1] + bh[br0 + c1] : -1e30f;
            sacc[mi][nj][2] = (c0 < NTOK) ? sacc[mi][nj][2] + bh[br1 + c0] : -1e30f;
            sacc[mi][nj][3] = (c1 < NTOK) ? sacc[mi][nj][3] + bh[br1 + c1] : -1e30f;
        }
    }

    // ---- softmax in registers (rows live in 4-lane t-groups) ----
    #pragma unroll
    for (int mi = 0; mi < 2; mi++) {
        float m0 = -1e30f, m1 = -1e30f;
        #pragma unroll
        for (int nj = 0; nj < 7; nj++) {
            m0 = fmaxf(m0, fmaxf(sacc[mi][nj][0], sacc[mi][nj][1]));
            m1 = fmaxf(m1, fmaxf(sacc[mi][nj][2], sacc[mi][nj][3]));
        }
        m0 = fmaxf(m0, __shfl_xor_sync(0xffffffffu, m0, 1));
        m0 = fmaxf(m0, __shfl_xor_sync(0xffffffffu, m0, 2));
        m1 = fmaxf(m1, __shfl_xor_sync(0xffffffffu, m1, 1));
        m1 = fmaxf(m1, __shfl_xor_sync(0xffffffffu, m1, 2));
        float s0 = 0.f, s1 = 0.f;
        #pragma unroll
        for (int nj = 0; nj < 7; nj++) {
            sacc[mi][nj][0] = __expf(sacc[mi][nj][0] - m0); s0 += sacc[mi][nj][0];
            sacc[mi][nj][1] = __expf(sacc[mi][nj][1] - m0); s0 += sacc[mi][nj][1];
            sacc[mi][nj][2] = __expf(sacc[mi][nj][2] - m1); s1 += sacc[mi][nj][2];
            sacc[mi][nj][3] = __expf(sacc[mi][nj][3] - m1); s1 += sacc[mi][nj][3];
        }
        s0 += __shfl_xor_sync(0xffffffffu, s0, 1);
        s0 += __shfl_xor_sync(0xffffffffu, s0, 2);
        s1 += __shfl_xor_sync(0xffffffffu, s1, 1);
        s1 += __shfl_xor_sync(0xffffffffu, s1, 2);
        float i0 = 1.f / s0, i1 = 1.f / s1;
        #pragma unroll
        for (int nj = 0; nj < 7; nj++) {
            sacc[mi][nj][0] *= i0; sacc[mi][nj][1] *= i0;
            sacc[mi][nj][2] *= i1; sacc[mi][nj][3] *= i1;
        }
    }

    // ---- O = P V : P-fragments via t-group shuffles, V from smem ----
    float oacc[2][4][4];
    #pragma unroll
    for (int mi = 0; mi < 2; mi++)
        #pragma unroll
        for (int nd = 0; nd < 4; nd++)
            #pragma unroll
            for (int r = 0; r < 4; r++) oacc[mi][nd][r] = 0.f;

    const int src0 = (lane & ~3) | (t >> 1);
    const int src1 = src0 + 2;
    const bool odd = (t & 1);

    #pragma unroll
    for (int jt = 0; jt < 7; jt++) {
        uint32_t pa[2][4];
        #pragma unroll
        for (int mi = 0; mi < 2; mi++) {
            float e, o;
            e = __shfl_sync(0xffffffffu, sacc[mi][jt][0], src0);
            o = __shfl_sync(0xffffffffu, sacc[mi][jt][1], src0);
            pa[mi][0] = fautf(odd ? o : e);
            e = __shfl_sync(0xffffffffu, sacc[mi][jt][2], src0);
            o = __shfl_sync(0xffffffffu, sacc[mi][jt][3], src0);
            pa[mi][1] = fautf(odd ? o : e);
            e = __shfl_sync(0xffffffffu, sacc[mi][jt][0], src1);
            o = __shfl_sync(0xffffffffu, sacc[mi][jt][1], src1);
            pa[mi][2] = fautf(odd ? o : e);
            e = __shfl_sync(0xffffffffu, sacc[mi][jt][2], src1);
            o = __shfl_sync(0xffffffffu, sacc[mi][jt][3], src1);
            pa[mi][3] = fautf(odd ? o : e);
        }
        uint32_t bfr[4][2];
        #pragma unroll
        for (int nd = 0; nd < 4; nd++) {
            bfr[nd][0] = fau(V[(jt * 8 + t)     * HVS + nd * 8 + g]);
            bfr[nd][1] = fau(V[(jt * 8 + t + 4) * HVS + nd * 8 + g]);
        }
        #pragma unroll
        for (int mi = 0; mi < 2; mi++)
            #pragma unroll
            for (int nd = 0; nd < 4; nd++)
                mma_tf32(oacc[mi][nd], pa[mi], bfr[nd]);
    }

    // ---- store O (unrounded; proj GEMM rounds its A operand) ----
    #pragma unroll
    for (int mi = 0; mi < 2; mi++) {
        int r0 = mwarp * 32 + mi * 16 + g;
        int r1 = r0 + 8;
        #pragma unroll
        for (int nd = 0; nd < 4; nd++) {
            int d0 = nd * 8 + 2 * t;
            if (r0 < NTOK) {
                float2 v0 = make_float2(oacc[mi][nd][0], oacc[mi][nd][1]);
                *(float2*)(ctx + ((size_t)w * NTOK + r0) * CDIM + h * HDIM + d0) = v0;
            }
            if (r1 < NTOK) {
                float2 v1 = make_float2(oacc[mi][nd][2], oacc[mi][nd][3]);
                *(float2*)(ctx + ((size_t)w * NTOK + r1) * CDIM + h * HDIM + d0) = v1;
            }
        }
    }
}

// ---------------------------------------------------------------------------
// Launch
// ---------------------------------------------------------------------------
extern "C" void kernel_launch(void* const* d_in, const int* in_sizes, int n_in,
                              void* d_out, int out_size)
{
    const float* x     = (const float*)d_in[0];
    const float* Wqkv  = (const float*)d_in[1];
    const float* bqkv  = (const float*)d_in[2];
    const float* Wproj = (const float*)d_in[3];
    const float* bproj = (const float*)d_in[4];
    const float* table = (const float*)d_in[5];
    const int*   relix = (const int*)d_in[6];
    float* out = (float*)d_out;

    float *qkv, *ctx, *wq, *wp, *bias_g;
    cudaGetSymbolAddress((void**)&qkv, g_qkv);
    cudaGetSymbolAddress((void**)&ctx, g_ctx);
    cudaGetSymbolAddress((void**)&wq,  g_wq);
    cudaGetSymbolAddress((void**)&wp,  g_wp);
    cudaGetSymbolAddress((void**)&bias_g, g_bias);

    cudaFuncSetAttribute(gemm_tf32_kernel,
                         cudaFuncAttributeMaxDynamicSharedMemorySize, GEMM_SMEM);

    // 0) prep: round weights, build per-head bias table
    round_tf32_kernel<<<432, 256>>>((const float4*)Wqkv, (float4*)wq,
                                    (KDIM * N_QKV) / 4);
    round_tf32_kernel<<<144, 256>>>((const float4*)Wproj, (float4*)wp,
                                    (KDIM * CDIM) / 4);
    bias_build_kernel<<<(HEADS * NTOK * NTOK + 255) / 256, 256>>>(
        table, relix, bias_g);

    // 1) qkv = round(x @ W_qkv + b)   (M=200704, N=1152, K=384)
    gemm_tf32_kernel<<<dim3(N_QKV / 128, MROWS / 128), 256, GEMM_SMEM>>>(
        x, wq, bqkv, qkv, N_QKV, 1);

    // 2) attention (tensor-core), one block per (window, head-pair)
    attn_tc_kernel<<<dim3(BTOT, HEADS / 2), 128>>>(qkv, bias_g, ctx);

    // 3) out = ctx @ W_proj + b       (M=200704, N=384, K=384)
    gemm_tf32_kernel<<<dim3(CDIM / 128, MROWS / 128), 256, GEMM_SMEM>>>(
        ctx, wp, bproj, out, CDIM, 0);
}

// round 8
// speedup vs baseline: 2.0707x; 1.9691x over previous
#include <cuda_runtime.h>
#include <cuda_fp16.h>
#include <cstdint>
#include <cstddef>

// ---------------------------------------------------------------------------
// Problem constants
// ---------------------------------------------------------------------------
#define BTOT   4096
#define NTOK   49
#define CDIM   384
#define HEADS  12
#define HDIM   32
#define MROWS  (BTOT * NTOK)        // 200704
#define KDIM   384
#define N_QKV  1152

// Scratch (__device__ globals: the allowed alloc-free pattern)
__device__ __half g_qkvh[(size_t)MROWS * N_QKV];  // 462 MB
__device__ __half g_ctxh[(size_t)MROWS * CDIM];   // 154 MB
__device__ __half g_xh  [(size_t)MROWS * KDIM];   // 154 MB
__device__ __half g_wqh [(size_t)N_QKV * KDIM];   // W_qkv^T as half [N][K]
__device__ __half g_wph [(size_t)CDIM * KDIM];    // W_proj^T as half [N][K]
__device__ float  g_bias[(size_t)HEADS * NTOK * NTOK];

// ---------------------------------------------------------------------------
// Helpers
// ---------------------------------------------------------------------------
__device__ __forceinline__ uint32_t smem_u32(const void* p) {
    return (uint32_t)__cvta_generic_to_shared(p);
}
__device__ __forceinline__ void cp16(uint32_t dst, const void* src) {
    asm volatile("cp.async.cg.shared.global [%0], [%1], 16;" :: "r"(dst), "l"(src));
}
__device__ __forceinline__ void cp_commit() {
    asm volatile("cp.async.commit_group;" ::: "memory");
}
__device__ __forceinline__ void cp_wait2() {
    asm volatile("cp.async.wait_group 2;" ::: "memory");
}
__device__ __forceinline__ void cp_wait0() {
    asm volatile("cp.async.wait_group 0;" ::: "memory");
}

__device__ __forceinline__ void ldsm4(uint32_t& r0, uint32_t& r1, uint32_t& r2,
                                      uint32_t& r3, uint32_t a) {
    asm volatile("ldmatrix.sync.aligned.m8n8.x4.shared.b16 {%0,%1,%2,%3}, [%4];"
                 : "=r"(r0), "=r"(r1), "=r"(r2), "=r"(r3) : "r"(a));
}
__device__ __forceinline__ void ldsm4t(uint32_t& r0, uint32_t& r1, uint32_t& r2,
                                       uint32_t& r3, uint32_t a) {
    asm volatile("ldmatrix.sync.aligned.m8n8.x4.trans.shared.b16 {%0,%1,%2,%3}, [%4];"
                 : "=r"(r0), "=r"(r1), "=r"(r2), "=r"(r3) : "r"(a));
}

__device__ __forceinline__ void mma_f16(float c[4], const uint32_t a[4],
                                        const uint32_t b[2]) {
    asm volatile(
        "mma.sync.aligned.m16n8k16.row.col.f32.f16.f16.f32 "
        "{%0,%1,%2,%3}, {%4,%5,%6,%7}, {%8,%9}, {%0,%1,%2,%3};"
        : "+f"(c[0]), "+f"(c[1]), "+f"(c[2]), "+f"(c[3])
        : "r"(a[0]), "r"(a[1]), "r"(a[2]), "r"(a[3]), "r"(b[0]), "r"(b[1]));
}

__device__ __forceinline__ uint32_t packh2(float lo, float hi) {
    __half2 h = __floats2half2_rn(lo, hi);
    return *(uint32_t*)&h;
}

// ---------------------------------------------------------------------------
// Prep kernels
// ---------------------------------------------------------------------------
__global__ void f2h_kernel(const float4* __restrict__ in, uint2* __restrict__ out,
                           int n4)
{
    for (int i = blockIdx.x * blockDim.x + threadIdx.x; i < n4;
         i += gridDim.x * blockDim.x) {
        float4 v = in[i];
        out[i] = make_uint2(packh2(v.x, v.y), packh2(v.z, v.w));
    }
}

// Wt[n][k] = (half)W[k][n];  W is K x N row-major, K,N multiples of 32
__global__ void transpose_h_kernel(const float* __restrict__ W,
                                   __half* __restrict__ Wt, int K, int N)
{
    __shared__ float t[32][33];
    int kb = blockIdx.y * 32, nb = blockIdx.x * 32;
    int x = threadIdx.x, y = threadIdx.y;
    #pragma unroll
    for (int i = y; i < 32; i += 8)
        t[i][x] = W[(size_t)(kb + i) * N + nb + x];
    __syncthreads();
    #pragma unroll
    for (int i = y; i < 32; i += 8)
        Wt[(size_t)(nb + i) * K + kb + x] = __float2half_rn(t[x][i]);
}

__global__ void bias_build_kernel(const float* __restrict__ table,
                                  const int* __restrict__ relix,
                                  float* __restrict__ bias_g)
{
    int idx = blockIdx.x * blockDim.x + threadIdx.x;
    if (idx < HEADS * NTOK * NTOK) {
        int h = idx / (NTOK * NTOK), ij = idx % (NTOK * NTOK);
        bias_g[idx] = table[relix[ij] * HEADS + h];
    }
}

// ---------------------------------------------------------------------------
// fp16 GEMM: C[M x N] = A[M x 384] @ Bt[N x 384]^T + bias
// A, Bt half; acc f32. CTA 128x128, 128 thr, 4 warps (2x2), warp tile 64x64.
// BK=32 halfs, 3-stage cp.async; ldmatrix fragments; smem stride 40 halfs.
// half_out: 1 -> write half (qkv/ctx), 0 -> write f32 (final out).
// ---------------------------------------------------------------------------
#define HST 40                        // smem row stride in halfs (80 B)
#define TILE_B (128 * 80)             // 10240 bytes per operand tile
#define STG_B  (2 * TILE_B)           // 20480
#define GEMM_SMEM (3 * STG_B)         // 61440

__global__ void __launch_bounds__(128, 3)
gemm_f16_kernel(const __half* __restrict__ A, const __half* __restrict__ Bt,
                const float* __restrict__ bias, void* __restrict__ C,
                int Ncols, int half_out)
{
    extern __shared__ char smem[];
    const uint32_t sb = smem_u32(smem);

    const int tid  = threadIdx.x;
    const int warp = tid >> 5, lane = tid & 31;
    const int wm   = warp >> 1, wn = warp & 1;
    const int g    = lane >> 2, t = lane & 3;
    const int m0   = blockIdx.y * 128;
    const int n0   = blockIdx.x * 128;

    float acc[4][8][4];
    #pragma unroll
    for (int mi = 0; mi < 4; mi++)
        #pragma unroll
        for (int nj = 0; nj < 8; nj++)
            #pragma unroll
            for (int r = 0; r < 4; r++) acc[mi][nj][r] = 0.f;

    const char* gA = (const char*)A + (size_t)m0 * 768;   // 384 halfs/row
    const char* gB = (const char*)Bt + (size_t)n0 * 768;

    auto load_stage = [&](int kt, int s) {
        const uint32_t base = sb + s * STG_B;
        #pragma unroll
        for (int j = 0; j < 4; j++) {
            int c = tid + j * 128;                // 0..511
            int row = c >> 2, ch = c & 3;
            cp16(base + row * 80 + ch * 16,
                 gA + (size_t)row * 768 + kt * 64 + ch * 16);
        }
        #pragma unroll
        for (int j = 0; j < 4; j++) {
            int c = tid + j * 128;
            int row = c >> 2, ch = c & 3;
            cp16(base + TILE_B + row * 80 + ch * 16,
                 gB + (size_t)row * 768 + kt * 64 + ch * 16);
        }
    };

    auto compute = [&](int s) {
        const uint32_t aB = sb + s * STG_B;
        const uint32_t bB = aB + TILE_B;
        #pragma unroll
        for (int ks = 0; ks < 2; ks++) {
            uint32_t af[4][4], bf[8][2];
            #pragma unroll
            for (int mi = 0; mi < 4; mi++) {
                int mb = wm * 64 + mi * 16;
                uint32_t addr = aB + (mb + (lane & 15)) * 80 + ks * 32
                              + (lane >> 4) * 16;
                ldsm4(af[mi][0], af[mi][1], af[mi][2], af[mi][3], addr);
            }
            #pragma unroll
            for (int p = 0; p < 4; p++) {
                int j0 = wn * 64 + p * 16;
                uint32_t addr = bB + (j0 + (lane & 7) + ((lane >> 4) << 3)) * 80
                              + ks * 32 + ((lane >> 3) & 1) * 16;
                ldsm4(bf[2 * p][0], bf[2 * p][1], bf[2 * p + 1][0],
                      bf[2 * p + 1][1], addr);
            }
            #pragma unroll
            for (int mi = 0; mi < 4; mi++)
                #pragma unroll
                for (int nj = 0; nj < 8; nj++)
                    mma_f16(acc[mi][nj], af[mi], bf[nj]);
        }
    };

    load_stage(0, 0); cp_commit();
    load_stage(1, 1); cp_commit();
    load_stage(2, 2); cp_commit();

    #pragma unroll 1
    for (int kt = 0; kt < 12; kt++) {
        int s = kt % 3;
        cp_wait2();
        __syncthreads();
        compute(s);
        __syncthreads();
        if (kt + 3 < 12) load_stage(kt + 3, s);
        cp_commit();
    }

    // epilogue
    #pragma unroll
    for (int mi = 0; mi < 4; mi++) {
        #pragma unroll
        for (int nj = 0; nj < 8; nj++) {
            int row = m0 + wm * 64 + mi * 16 + g;
            int col = n0 + wn * 64 + nj * 8 + 2 * t;
            float2 bb = *(const float2*)(bias + col);
            float a0 = acc[mi][nj][0] + bb.x, a1 = acc[mi][nj][1] + bb.y;
            float a2 = acc[mi][nj][2] + bb.x, a3 = acc[mi][nj][3] + bb.y;
            if (half_out) {
                __half* Ch = (__half*)C;
                *(uint32_t*)(Ch + (size_t)row * Ncols + col)       = packh2(a0, a1);
                *(uint32_t*)(Ch + (size_t)(row + 8) * Ncols + col) = packh2(a2, a3);
            } else {
                float* Cf = (float*)C;
                *(float2*)(Cf + (size_t)row * Ncols + col)       = make_float2(a0, a1);
                *(float2*)(Cf + (size_t)(row + 8) * Ncols + col) = make_float2(a2, a3);
            }
        }
    }
}

// ---------------------------------------------------------------------------
// fp16 tensor-core attention. Block = (window, head-pair): 128 thr, 4 warps.
// Warp (hh, mwarp): head hh, rows [mwarp*32, +32) of M padded to 64.
// S = Q K^T (m16n8k16, ldmatrix); scale+bias+guard in f32; register softmax;
// P acc maps DIRECTLY to fp16 A-fragments (no shuffles); O = P V with
// ldmatrix.trans on row-major V. qkv/ctx are half.
// ---------------------------------------------------------------------------
__global__ void __launch_bounds__(128, 3)
attn_h_kernel(const __half* __restrict__ qkvh, const float* __restrict__ bias_g,
              __half* __restrict__ ctxh)
{
    __shared__ __align__(16) __half q_s[2][64 * HST];
    __shared__ __align__(16) __half k_s[2][64 * HST];
    __shared__ __align__(16) __half v_s[2][64 * HST];

    const int w  = blockIdx.x;
    const int hp = blockIdx.y;
    const int tid = threadIdx.x, wid = tid >> 5, lane = tid & 31;
    const int hh = wid >> 1, mwarp = wid & 1;
    const int h  = hp * 2 + hh;
    const int g  = lane >> 2, t = lane & 3;
    const float scale = 0.1767766952966369f;   // 32^-0.5

    // zero-fill pad rows 49..63 of all six matrices (75 uint4 each)
    #pragma unroll
    for (int hl = 0; hl < 2; hl++) {
        uint4 z = make_uint4(0u, 0u, 0u, 0u);
        for (int i = tid; i < 75; i += 128) {
            ((uint4*)(q_s[hl] + 49 * HST))[i] = z;
            ((uint4*)(k_s[hl] + 49 * HST))[i] = z;
            ((uint4*)(v_s[hl] + 49 * HST))[i] = z;
        }
    }

    // cp.async q/k/v rows 0..48 (4x16B chunks per row) for both heads
    #pragma unroll
    for (int hl = 0; hl < 2; hl++) {
        const char* base = (const char*)(qkvh + (size_t)w * NTOK * N_QKV
                                         + (size_t)(hp * 2 + hl) * HDIM);
        uint32_t sq = smem_u32(q_s[hl]), sk = smem_u32(k_s[hl]), sv = smem_u32(v_s[hl]);
        for (int idx = tid; idx < 588; idx += 128) {
            int mat = idx / 196, rem = idx - mat * 196;
            int r = rem >> 2, ch = rem & 3;
            uint32_t dst = (mat == 0 ? sq : mat == 1 ? sk : sv) + r * 80 + ch * 16;
            cp16(dst, base + (size_t)r * 2304 + mat * 768 + ch * 16);
        }
    }
    cp_commit();
    cp_wait0();
    __syncthreads();

    const uint32_t Q = smem_u32(q_s[hh]);
    const uint32_t K = smem_u32(k_s[hh]);
    const uint32_t V = smem_u32(v_s[hh]);

    // ---- S = Q K^T : 2 k-steps x 2 m-tiles x 8 n-tiles ----
    float sacc[2][8][4];
    #pragma unroll
    for (int mi = 0; mi < 2; mi++)
        #pragma unroll
        for (int nj = 0; nj < 8; nj++)
            #pragma unroll
            for (int r = 0; r < 4; r++) sacc[mi][nj][r] = 0.f;

    #pragma unroll
    for (int ks = 0; ks < 2; ks++) {
        uint32_t af[2][4], bf[8][2];
        #pragma unroll
        for (int mi = 0; mi < 2; mi++) {
            int mb = mwarp * 32 + mi * 16;
            uint32_t addr = Q + (mb + (lane & 15)) * 80 + ks * 32 + (lane >> 4) * 16;
            ldsm4(af[mi][0], af[mi][1], af[mi][2], af[mi][3], addr);
        }
        #pragma unroll
        for (int p = 0; p < 4; p++) {
            uint32_t addr = K + (p * 16 + (lane & 7) + ((lane >> 4) << 3)) * 80
                          + ks * 32 + ((lane >> 3) & 1) * 16;
            ldsm4(bf[2 * p][0], bf[2 * p][1], bf[2 * p + 1][0], bf[2 * p + 1][1], addr);
        }
        #pragma unroll
        for (int mi = 0; mi < 2; mi++)
            #pragma unroll
            for (int nj = 0; nj < 8; nj++)
                mma_f16(sacc[mi][nj], af[mi], bf[nj]);
    }

    // ---- scale + bias + column guard ----
    const float* bh = bias_g + (size_t)h * (NTOK * NTOK);
    #pragma unroll
    for (int mi = 0; mi < 2; mi++) {
        int r0 = mwarp * 32 + mi * 16 + g;
        int r1 = r0 + 8;
        int br0 = min(r0, NTOK - 1) * NTOK;
        int br1 = min(r1, NTOK - 1) * NTOK;
        #pragma unroll
        for (int nj = 0; nj < 8; nj++) {
            int c0 = nj * 8 + 2 * t, c1 = c0 + 1;
            sacc[mi][nj][0] = (c0 < NTOK) ? sacc[mi][nj][0] * scale + bh[br0 + c0] : -1e30f;
            sacc[mi][nj][1] = (c1 < NTOK) ? sacc[mi][nj][1] * scale + bh[br0 + c1] : -1e30f;
            sacc[mi][nj][2] = (c0 < NTOK) ? sacc[mi][nj][2] * scale + bh[br1 + c0] : -1e30f;
            sacc[mi][nj][3] = (c1 < NTOK) ? sacc[mi][nj][3] * scale + bh[br1 + c1] : -1e30f;
        }
    }

    // ---- register softmax (rows live in 4-lane t-groups) ----
    #pragma unroll
    for (int mi = 0; mi < 2; mi++) {
        float m0 = -1e30f, m1 = -1e30f;
        #pragma unroll
        for (int nj = 0; nj < 8; nj++) {
            m0 = fmaxf(m0, fmaxf(sacc[mi][nj][0], sacc[mi][nj][1]));
            m1 = fmaxf(m1, fmaxf(sacc[mi][nj][2], sacc[mi][nj][3]));
        }
        m0 = fmaxf(m0, __shfl_xor_sync(0xffffffffu, m0, 1));
        m0 = fmaxf(m0, __shfl_xor_sync(0xffffffffu, m0, 2));
        m1 = fmaxf(m1, __shfl_xor_sync(0xffffffffu, m1, 1));
        m1 = fmaxf(m1, __shfl_xor_sync(0xffffffffu, m1, 2));
        float s0 = 0.f, s1 = 0.f;
        #pragma unroll
        for (int nj = 0; nj < 8; nj++) {
            sacc[mi][nj][0] = __expf(sacc[mi][nj][0] - m0); s0 += sacc[mi][nj][0];
            sacc[mi][nj][1] = __expf(sacc[mi][nj][1] - m0); s0 += sacc[mi][nj][1];
            sacc[mi][nj][2] = __expf(sacc[mi][nj][2] - m1); s1 += sacc[mi][nj][2];
            sacc[mi][nj][3] = __expf(sacc[mi][nj][3] - m1); s1 += sacc[mi][nj][3];
        }
        s0 += __shfl_xor_sync(0xffffffffu, s0, 1);
        s0 += __shfl_xor_sync(0xffffffffu, s0, 2);
        s1 += __shfl_xor_sync(0xffffffffu, s1, 1);
        s1 += __shfl_xor_sync(0xffffffffu, s1, 2);
        float i0 = 1.f / s0, i1 = 1.f / s1;
        #pragma unroll
        for (int nj = 0; nj < 8; nj++) {
            sacc[mi][nj][0] *= i0; sacc[mi][nj][1] *= i0;
            sacc[mi][nj][2] *= i1; sacc[mi][nj][3] *= i1;
        }
    }

    // ---- O = P V : P acc packs directly into fp16 A-fragments ----
    float oacc[2][4][4];
    #pragma unroll
    for (int mi = 0; mi < 2; mi++)
        #pragma unroll
        for (int nd = 0; nd < 4; nd++)
            #pragma unroll
            for (int r = 0; r < 4; r++) oacc[mi][nd][r] = 0.f;

    #pragma unroll
    for (int jt = 0; jt < 4; jt++) {
        uint32_t bf[4][2];
        #pragma unroll
        for (int p = 0; p < 2; p++) {
            uint32_t addr = V + (jt * 16 + (lane & 7) + (((lane >> 3) & 1) << 3)) * 80
                          + p * 32 + ((lane >> 4) << 4);
            ldsm4t(bf[2 * p][0], bf[2 * p][1], bf[2 * p + 1][0], bf[2 * p + 1][1], addr);
        }
        uint32_t pa[2][4];
        #pragma unroll
        for (int mi = 0; mi < 2; mi++) {
            pa[mi][0] = packh2(sacc[mi][2 * jt][0],     sacc[mi][2 * jt][1]);
            pa[mi][1] = packh2(sacc[mi][2 * jt][2],     sacc[mi][2 * jt][3]);
            pa[mi][2] = packh2(sacc[mi][2 * jt + 1][0], sacc[mi][2 * jt + 1][1]);
            pa[mi][3] = packh2(sacc[mi][2 * jt + 1][2], sacc[mi][2 * jt + 1][3]);
        }
        #pragma unroll
        for (int mi = 0; mi < 2; mi++)
            #pragma unroll
            for (int nd = 0; nd < 4; nd++)
                mma_f16(oacc[mi][nd], pa[mi], bf[nd]);
    }

    // ---- store O as half2 ----
    #pragma unroll
    for (int mi = 0; mi < 2; mi++) {
        int r0 = mwarp * 32 + mi * 16 + g;
        int r1 = r0 + 8;
        #pragma unroll
        for (int nd = 0; nd < 4; nd++) {
            int d0 = nd * 8 + 2 * t;
            if (r0 < NTOK)
                *(uint32_t*)(ctxh + ((size_t)w * NTOK + r0) * CDIM + h * HDIM + d0)
                    = packh2(oacc[mi][nd][0], oacc[mi][nd][1]);
            if (r1 < NTOK)
                *(uint32_t*)(ctxh + ((size_t)w * NTOK + r1) * CDIM + h * HDIM + d0)
                    = packh2(oacc[mi][nd][2], oacc[mi][nd][3]);
        }
    }
}

// ---------------------------------------------------------------------------
// Launch
// ---------------------------------------------------------------------------
extern "C" void kernel_launch(void* const* d_in, const int* in_sizes, int n_in,
                              void* d_out, int out_size)
{
    const float* x     = (const float*)d_in[0];
    const float* Wqkv  = (const float*)d_in[1];
    const float* bqkv  = (const float*)d_in[2];
    const float* Wproj = (const float*)d_in[3];
    const float* bproj = (const float*)d_in[4];
    const float* table = (const float*)d_in[5];
    const int*   relix = (const int*)d_in[6];
    float* out = (float*)d_out;

    __half *qkvh, *ctxh, *xh, *wqh, *wph;
    float* bias_g;
    cudaGetSymbolAddress((void**)&qkvh, g_qkvh);
    cudaGetSymbolAddress((void**)&ctxh, g_ctxh);
    cudaGetSymbolAddress((void**)&xh,   g_xh);
    cudaGetSymbolAddress((void**)&wqh,  g_wqh);
    cudaGetSymbolAddress((void**)&wph,  g_wph);
    cudaGetSymbolAddress((void**)&bias_g, g_bias);

    cudaFuncSetAttribute(gemm_f16_kernel,
                         cudaFuncAttributeMaxDynamicSharedMemorySize, GEMM_SMEM);

    // 0) prep
    f2h_kernel<<<4096, 256>>>((const float4*)x, (uint2*)xh, (MROWS * KDIM) / 4);
    transpose_h_kernel<<<dim3(N_QKV / 32, KDIM / 32), dim3(32, 8)>>>(
        Wqkv, wqh, KDIM, N_QKV);
    transpose_h_kernel<<<dim3(CDIM / 32, KDIM / 32), dim3(32, 8)>>>(
        Wproj, wph, KDIM, CDIM);
    bias_build_kernel<<<(HEADS * NTOK * NTOK + 255) / 256, 256>>>(
        table, relix, bias_g);

    // 1) qkv = half(x @ W_qkv + b)   (M=200704, N=1152, K=384)
    gemm_f16_kernel<<<dim3(N_QKV / 128, MROWS / 128), 128, GEMM_SMEM>>>(
        xh, wqh, bqkv, qkvh, N_QKV, 1);

    // 2) attention (fp16 tensor-core), one block per (window, head-pair)
    attn_h_kernel<<<dim3(BTOT, HEADS / 2), 128>>>(qkvh, bias_g, ctxh);

    // 3) out = ctx @ W_proj + b      (M=200704, N=384, K=384), f32 out
    gemm_f16_kernel<<<dim3(CDIM / 128, MROWS / 128), 128, GEMM_SMEM>>>(
        ctxh, wph, bproj, out, CDIM, 0);
}

// round 9
// speedup vs baseline: 2.1567x; 1.0415x over previous
#include <cuda_runtime.h>
#include <cuda_fp16.h>
#include <cstdint>
#include <cstddef>

// ---------------------------------------------------------------------------
// Problem constants
// ---------------------------------------------------------------------------
#define BTOT   4096
#define NTOK   49
#define CDIM   384
#define HEADS  12
#define HDIM   32
#define MROWS  (BTOT * NTOK)        // 200704
#define KDIM   384
#define N_QKV  1152

// Scratch (__device__ globals: the allowed alloc-free pattern)
__device__ __half g_qkvh[(size_t)MROWS * N_QKV];  // 462 MB
__device__ __half g_ctxh[(size_t)MROWS * CDIM];   // 154 MB
__device__ __half g_xh  [(size_t)MROWS * KDIM];   // 154 MB
__device__ __half g_wqh [(size_t)N_QKV * KDIM];   // W_qkv^T as half [N][K]
__device__ __half g_wph [(size_t)CDIM * KDIM];    // W_proj^T as half [N][K]
__device__ float  g_bias[(size_t)HEADS * NTOK * NTOK];

// ---------------------------------------------------------------------------
// Helpers
// ---------------------------------------------------------------------------
__device__ __forceinline__ uint32_t smem_u32(const void* p) {
    return (uint32_t)__cvta_generic_to_shared(p);
}
__device__ __forceinline__ void cp16(uint32_t dst, const void* src) {
    asm volatile("cp.async.cg.shared.global [%0], [%1], 16;" :: "r"(dst), "l"(src));
}
__device__ __forceinline__ void cp_commit() {
    asm volatile("cp.async.commit_group;" ::: "memory");
}
__device__ __forceinline__ void cp_wait1() {
    asm volatile("cp.async.wait_group 1;" ::: "memory");
}
__device__ __forceinline__ void cp_wait0() {
    asm volatile("cp.async.wait_group 0;" ::: "memory");
}

__device__ __forceinline__ void ldsm4(uint32_t& r0, uint32_t& r1, uint32_t& r2,
                                      uint32_t& r3, uint32_t a) {
    asm volatile("ldmatrix.sync.aligned.m8n8.x4.shared.b16 {%0,%1,%2,%3}, [%4];"
                 : "=r"(r0), "=r"(r1), "=r"(r2), "=r"(r3) : "r"(a));
}
__device__ __forceinline__ void ldsm4t(uint32_t& r0, uint32_t& r1, uint32_t& r2,
                                       uint32_t& r3, uint32_t a) {
    asm volatile("ldmatrix.sync.aligned.m8n8.x4.trans.shared.b16 {%0,%1,%2,%3}, [%4];"
                 : "=r"(r0), "=r"(r1), "=r"(r2), "=r"(r3) : "r"(a));
}

__device__ __forceinline__ void mma_f16(float c[4], const uint32_t a[4],
                                        const uint32_t b[2]) {
    asm volatile(
        "mma.sync.aligned.m16n8k16.row.col.f32.f16.f16.f32 "
        "{%0,%1,%2,%3}, {%4,%5,%6,%7}, {%8,%9}, {%0,%1,%2,%3};"
        : "+f"(c[0]), "+f"(c[1]), "+f"(c[2]), "+f"(c[3])
        : "r"(a[0]), "r"(a[1]), "r"(a[2]), "r"(a[3]), "r"(b[0]), "r"(b[1]));
}

__device__ __forceinline__ uint32_t packh2(float lo, float hi) {
    __half2 h = __floats2half2_rn(lo, hi);
    return *(uint32_t*)&h;
}

// ---------------------------------------------------------------------------
// Prep kernels
// ---------------------------------------------------------------------------
__global__ void f2h_kernel(const float4* __restrict__ in, uint2* __restrict__ out,
                           int n4)
{
    for (int i = blockIdx.x * blockDim.x + threadIdx.x; i < n4;
         i += gridDim.x * blockDim.x) {
        float4 v = in[i];
        out[i] = make_uint2(packh2(v.x, v.y), packh2(v.z, v.w));
    }
}

// Wt[n][k] = (half)W[k][n];  W is K x N row-major, K,N multiples of 32
__global__ void transpose_h_kernel(const float* __restrict__ W,
                                   __half* __restrict__ Wt, int K, int N)
{
    __shared__ float t[32][33];
    int kb = blockIdx.y * 32, nb = blockIdx.x * 32;
    int x = threadIdx.x, y = threadIdx.y;
    #pragma unroll
    for (int i = y; i < 32; i += 8)
        t[i][x] = W[(size_t)(kb + i) * N + nb + x];
    __syncthreads();
    #pragma unroll
    for (int i = y; i < 32; i += 8)
        Wt[(size_t)(nb + i) * K + kb + x] = __float2half_rn(t[x][i]);
}

__global__ void bias_build_kernel(const float* __restrict__ table,
                                  const int* __restrict__ relix,
                                  float* __restrict__ bias_g)
{
    int idx = blockIdx.x * blockDim.x + threadIdx.x;
    if (idx < HEADS * NTOK * NTOK) {
        int h = idx / (NTOK * NTOK), ij = idx % (NTOK * NTOK);
        bias_g[idx] = table[relix[ij] * HEADS + h];
    }
}

// ---------------------------------------------------------------------------
// fp16 GEMM: C[M x N] = A[M x 384] @ Bt[N x 384]^T + bias
// CTA 128x128, 256 thr = 8 warps (4m x 2n), warp tile 32x64.
// BK=64 halfs (128 B/row), 2-stage cp.async, 6 k-iters.
// Smem stride 144 B = 128+16 -> rows rotate one bank-group: ldmatrix CF.
// 73.7 KB smem, <=128 regs -> 2 CTAs/SM = 16 warps.
// ---------------------------------------------------------------------------
#define GSTRB  144                    // smem row stride bytes (72 halfs)
#define TILE_B (128 * GSTRB)          // 18432 per operand tile
#define STG_B  (2 * TILE_B)           // 36864
#define GEMM_SMEM (2 * STG_B)         // 73728

__global__ void __launch_bounds__(256, 2)
gemm_f16_kernel(const __half* __restrict__ A, const __half* __restrict__ Bt,
                const float* __restrict__ bias, void* __restrict__ C,
                int Ncols, int half_out)
{
    extern __shared__ char smem[];
    const uint32_t sb = smem_u32(smem);

    const int tid  = threadIdx.x;
    const int warp = tid >> 5, lane = tid & 31;
    const int wm   = warp >> 1, wn = warp & 1;     // 4 x 2 warp grid
    const int g    = lane >> 2, t = lane & 3;
    const int m0   = blockIdx.y * 128;
    const int n0   = blockIdx.x * 128;

    float acc[2][8][4];
    #pragma unroll
    for (int mi = 0; mi < 2; mi++)
        #pragma unroll
        for (int nj = 0; nj < 8; nj++)
            #pragma unroll
            for (int r = 0; r < 4; r++) acc[mi][nj][r] = 0.f;

    const char* gA = (const char*)A + (size_t)m0 * 768;   // 384 halfs/row
    const char* gB = (const char*)Bt + (size_t)n0 * 768;

    // per k-tile: each operand row contributes 128 B (8 x 16B chunks)
    auto load_stage = [&](int kt, int s) {
        const uint32_t base = sb + s * STG_B;
        #pragma unroll
        for (int j = 0; j < 4; j++) {
            int c = tid + j * 256;                 // 0..1023
            int row = c >> 3, ch = c & 7;
            cp16(base + row * GSTRB + ch * 16,
                 gA + (size_t)row * 768 + kt * 128 + ch * 16);
        }
        #pragma unroll
        for (int j = 0; j < 4; j++) {
            int c = tid + j * 256;
            int row = c >> 3, ch = c & 7;
            cp16(base + TILE_B + row * GSTRB + ch * 16,
                 gB + (size_t)row * 768 + kt * 128 + ch * 16);
        }
    };

    auto compute = [&](int s) {
        const uint32_t aB = sb + s * STG_B;
        const uint32_t bB = aB + TILE_B;
        #pragma unroll
        for (int ks = 0; ks < 4; ks++) {           // 4 k-steps of 16 halfs
            uint32_t af[2][4], bf[8][2];
            #pragma unroll
            for (int mi = 0; mi < 2; mi++) {
                int mb = wm * 32 + mi * 16;
                uint32_t addr = aB + (mb + (lane & 15)) * GSTRB + ks * 32
                              + (lane >> 4) * 16;
                ldsm4(af[mi][0], af[mi][1], af[mi][2], af[mi][3], addr);
            }
            #pragma unroll
            for (int p = 0; p < 4; p++) {
                int j0 = wn * 64 + p * 16;
                uint32_t addr = bB + (j0 + (lane & 7) + ((lane >> 4) << 3)) * GSTRB
                              + ks * 32 + ((lane >> 3) & 1) * 16;
                ldsm4(bf[2 * p][0], bf[2 * p][1], bf[2 * p + 1][0],
                      bf[2 * p + 1][1], addr);
            }
            #pragma unroll
            for (int mi = 0; mi < 2; mi++)
                #pragma unroll
                for (int nj = 0; nj < 8; nj++)
                    mma_f16(acc[mi][nj], af[mi], bf[nj]);
        }
    };

    load_stage(0, 0); cp_commit();

    int s = 0;
    #pragma unroll 1
    for (int kt = 0; kt < 6; kt++) {
        if (kt + 1 < 6) { load_stage(kt + 1, s ^ 1); cp_commit(); }
        if (kt + 1 < 6) cp_wait1(); else cp_wait0();
        __syncthreads();
        compute(s);
        __syncthreads();
        s ^= 1;
    }

    // epilogue
    #pragma unroll
    for (int mi = 0; mi < 2; mi++) {
        #pragma unroll
        for (int nj = 0; nj < 8; nj++) {
            int row = m0 + wm * 32 + mi * 16 + g;
            int col = n0 + wn * 64 + nj * 8 + 2 * t;
            float2 bb = *(const float2*)(bias + col);
            float a0 = acc[mi][nj][0] + bb.x, a1 = acc[mi][nj][1] + bb.y;
            float a2 = acc[mi][nj][2] + bb.x, a3 = acc[mi][nj][3] + bb.y;
            if (half_out) {
                __half* Ch = (__half*)C;
                *(uint32_t*)(Ch + (size_t)row * Ncols + col)       = packh2(a0, a1);
                *(uint32_t*)(Ch + (size_t)(row + 8) * Ncols + col) = packh2(a2, a3);
            } else {
                float* Cf = (float*)C;
                *(float2*)(Cf + (size_t)row * Ncols + col)       = make_float2(a0, a1);
                *(float2*)(Cf + (size_t)(row + 8) * Ncols + col) = make_float2(a2, a3);
            }
        }
    }
}

// ---------------------------------------------------------------------------
// fp16 tensor-core attention (validated round-8 version, unchanged).
// Block = (window, head-pair): 128 thr, 4 warps.
// ---------------------------------------------------------------------------
#define HST 40
__global__ void __launch_bounds__(128, 3)
attn_h_kernel(const __half* __restrict__ qkvh, const float* __restrict__ bias_g,
              __half* __restrict__ ctxh)
{
    __shared__ __align__(16) __half q_s[2][64 * HST];
    __shared__ __align__(16) __half k_s[2][64 * HST];
    __shared__ __align__(16) __half v_s[2][64 * HST];

    const int w  = blockIdx.x;
    const int hp = blockIdx.y;
    const int tid = threadIdx.x, wid = tid >> 5, lane = tid & 31;
    const int hh = wid >> 1, mwarp = wid & 1;
    const int h  = hp * 2 + hh;
    const int g  = lane >> 2, t = lane & 3;
    const float scale = 0.1767766952966369f;   // 32^-0.5

    #pragma unroll
    for (int hl = 0; hl < 2; hl++) {
        uint4 z = make_uint4(0u, 0u, 0u, 0u);
        for (int i = tid; i < 75; i += 128) {
            ((uint4*)(q_s[hl] + 49 * HST))[i] = z;
            ((uint4*)(k_s[hl] + 49 * HST))[i] = z;
            ((uint4*)(v_s[hl] + 49 * HST))[i] = z;
        }
    }

    #pragma unroll
    for (int hl = 0; hl < 2; hl++) {
        const char* base = (const char*)(qkvh + (size_t)w * NTOK * N_QKV
                                         + (size_t)(hp * 2 + hl) * HDIM);
        uint32_t sq = smem_u32(q_s[hl]), sk = smem_u32(k_s[hl]), sv = smem_u32(v_s[hl]);
        for (int idx = tid; idx < 588; idx += 128) {
            int mat = idx / 196, rem = idx - mat * 196;
            int r = rem >> 2, ch = rem & 3;
            uint32_t dst = (mat == 0 ? sq : mat == 1 ? sk : sv) + r * 80 + ch * 16;
            cp16(dst, base + (size_t)r * 2304 + mat * 768 + ch * 16);
        }
    }
    cp_commit();
    cp_wait0();
    __syncthreads();

    const uint32_t Q = smem_u32(q_s[hh]);
    const uint32_t K = smem_u32(k_s[hh]);
    const uint32_t V = smem_u32(v_s[hh]);

    float sacc[2][8][4];
    #pragma unroll
    for (int mi = 0; mi < 2; mi++)
        #pragma unroll
        for (int nj = 0; nj < 8; nj++)
            #pragma unroll
            for (int r = 0; r < 4; r++) sacc[mi][nj][r] = 0.f;

    #pragma unroll
    for (int ks = 0; ks < 2; ks++) {
        uint32_t af[2][4], bf[8][2];
        #pragma unroll
        for (int mi = 0; mi < 2; mi++) {
            int mb = mwarp * 32 + mi * 16;
            uint32_t addr = Q + (mb + (lane & 15)) * 80 + ks * 32 + (lane >> 4) * 16;
            ldsm4(af[mi][0], af[mi][1], af[mi][2], af[mi][3], addr);
        }
        #pragma unroll
        for (int p = 0; p < 4; p++) {
            uint32_t addr = K + (p * 16 + (lane & 7) + ((lane >> 4) << 3)) * 80
                          + ks * 32 + ((lane >> 3) & 1) * 16;
            ldsm4(bf[2 * p][0], bf[2 * p][1], bf[2 * p + 1][0], bf[2 * p + 1][1], addr);
        }
        #pragma unroll
        for (int mi = 0; mi < 2; mi++)
            #pragma unroll
            for (int nj = 0; nj < 8; nj++)
                mma_f16(sacc[mi][nj], af[mi], bf[nj]);
    }

    const float* bh = bias_g + (size_t)h * (NTOK * NTOK);
    #pragma unroll
    for (int mi = 0; mi < 2; mi++) {
        int r0 = mwarp * 32 + mi * 16 + g;
        int r1 = r0 + 8;
        int br0 = min(r0, NTOK - 1) * NTOK;
        int br1 = min(r1, NTOK - 1) * NTOK;
        #pragma unroll
        for (int nj = 0; nj < 8; nj++) {
            int c0 = nj * 8 + 2 * t, c1 = c0 + 1;
            sacc[mi][nj][0] = (c0 < NTOK) ? sacc[mi][nj][0] * scale + bh[br0 + c0] : -1e30f;
            sacc[mi][nj][1] = (c1 < NTOK) ? sacc[mi][nj][1] * scale + bh[br0 + c1] : -1e30f;
            sacc[mi][nj][2] = (c0 < NTOK) ? sacc[mi][nj][2] * scale + bh[br1 + c0] : -1e30f;
            sacc[mi][nj][3] = (c1 < NTOK) ? sacc[mi][nj][3] * scale + bh[br1 + c1] : -1e30f;
        }
    }

    #pragma unroll
    for (int mi = 0; mi < 2; mi++) {
        float m0 = -1e30f, m1 = -1e30f;
        #pragma unroll
        for (int nj = 0; nj < 8; nj++) {
            m0 = fmaxf(m0, fmaxf(sacc[mi][nj][0], sacc[mi][nj][1]));
            m1 = fmaxf(m1, fmaxf(sacc[mi][nj][2], sacc[mi][nj][3]));
        }
        m0 = fmaxf(m0, __shfl_xor_sync(0xffffffffu, m0, 1));
        m0 = fmaxf(m0, __shfl_xor_sync(0xffffffffu, m0, 2));
        m1 = fmaxf(m1, __shfl_xor_sync(0xffffffffu, m1, 1));
        m1 = fmaxf(m1, __shfl_xor_sync(0xffffffffu, m1, 2));
        float s0 = 0.f, s1 = 0.f;
        #pragma unroll
        for (int nj = 0; nj < 8; nj++) {
            sacc[mi][nj][0] = __expf(sacc[mi][nj][0] - m0); s0 += sacc[mi][nj][0];
            sacc[mi][nj][1] = __expf(sacc[mi][nj][1] - m0); s0 += sacc[mi][nj][1];
            sacc[mi][nj][2] = __expf(sacc[mi][nj][2] - m1); s1 += sacc[mi][nj][2];
            sacc[mi][nj][3] = __expf(sacc[mi][nj][3] - m1); s1 += sacc[mi][nj][3];
        }
        s0 += __shfl_xor_sync(0xffffffffu, s0, 1);
        s0 += __shfl_xor_sync(0xffffffffu, s0, 2);
        s1 += __shfl_xor_sync(0xffffffffu, s1, 1);
        s1 += __shfl_xor_sync(0xffffffffu, s1, 2);
        float i0 = 1.f / s0, i1 = 1.f / s1;
        #pragma unroll
        for (int nj = 0; nj < 8; nj++) {
            sacc[mi][nj][0] *= i0; sacc[mi][nj][1] *= i0;
            sacc[mi][nj][2] *= i1; sacc[mi][nj][3] *= i1;
        }
    }

    float oacc[2][4][4];
    #pragma unroll
    for (int mi = 0; mi < 2; mi++)
        #pragma unroll
        for (int nd = 0; nd < 4; nd++)
            #pragma unroll
            for (int r = 0; r < 4; r++) oacc[mi][nd][r] = 0.f;

    #pragma unroll
    for (int jt = 0; jt < 4; jt++) {
        uint32_t bf[4][2];
        #pragma unroll
        for (int p = 0; p < 2; p++) {
            uint32_t addr = V + (jt * 16 + (lane & 7) + (((lane >> 3) & 1) << 3)) * 80
                          + p * 32 + ((lane >> 4) << 4);
            ldsm4t(bf[2 * p][0], bf[2 * p][1], bf[2 * p + 1][0], bf[2 * p + 1][1], addr);
        }
        uint32_t pa[2][4];
        #pragma unroll
        for (int mi = 0; mi < 2; mi++) {
            pa[mi][0] = packh2(sacc[mi][2 * jt][0],     sacc[mi][2 * jt][1]);
            pa[mi][1] = packh2(sacc[mi][2 * jt][2],     sacc[mi][2 * jt][3]);
            pa[mi][2] = packh2(sacc[mi][2 * jt + 1][0], sacc[mi][2 * jt + 1][1]);
            pa[mi][3] = packh2(sacc[mi][2 * jt + 1][2], sacc[mi][2 * jt + 1][3]);
        }
        #pragma unroll
        for (int mi = 0; mi < 2; mi++)
            #pragma unroll
            for (int nd = 0; nd < 4; nd++)
                mma_f16(oacc[mi][nd], pa[mi], bf[nd]);
    }

    #pragma unroll
    for (int mi = 0; mi < 2; mi++) {
        int r0 = mwarp * 32 + mi * 16 + g;
        int r1 = r0 + 8;
        #pragma unroll
        for (int nd = 0; nd < 4; nd++) {
            int d0 = nd * 8 + 2 * t;
            if (r0 < NTOK)
                *(uint32_t*)(ctxh + ((size_t)w * NTOK + r0) * CDIM + h * HDIM + d0)
                    = packh2(oacc[mi][nd][0], oacc[mi][nd][1]);
            if (r1 < NTOK)
                *(uint32_t*)(ctxh + ((size_t)w * NTOK + r1) * CDIM + h * HDIM + d0)
                    = packh2(oacc[mi][nd][2], oacc[mi][nd][3]);
        }
    }
}

// ---------------------------------------------------------------------------
// Launch
// ---------------------------------------------------------------------------
extern "C" void kernel_launch(void* const* d_in, const int* in_sizes, int n_in,
                              void* d_out, int out_size)
{
    const float* x     = (const float*)d_in[0];
    const float* Wqkv  = (const float*)d_in[1];
    const float* bqkv  = (const float*)d_in[2];
    const float* Wproj = (const float*)d_in[3];
    const float* bproj = (const float*)d_in[4];
    const float* table = (const float*)d_in[5];
    const int*   relix = (const int*)d_in[6];
    float* out = (float*)d_out;

    __half *qkvh, *ctxh, *xh, *wqh, *wph;
    float* bias_g;
    cudaGetSymbolAddress((void**)&qkvh, g_qkvh);
    cudaGetSymbolAddress((void**)&ctxh, g_ctxh);
    cudaGetSymbolAddress((void**)&xh,   g_xh);
    cudaGetSymbolAddress((void**)&wqh,  g_wqh);
    cudaGetSymbolAddress((void**)&wph,  g_wph);
    cudaGetSymbolAddress((void**)&bias_g, g_bias);

    cudaFuncSetAttribute(gemm_f16_kernel,
                         cudaFuncAttributeMaxDynamicSharedMemorySize, GEMM_SMEM);

    // 0) prep
    f2h_kernel<<<4096, 256>>>((const float4*)x, (uint2*)xh, (MROWS * KDIM) / 4);
    transpose_h_kernel<<<dim3(N_QKV / 32, KDIM / 32), dim3(32, 8)>>>(
        Wqkv, wqh, KDIM, N_QKV);
    transpose_h_kernel<<<dim3(CDIM / 32, KDIM / 32), dim3(32, 8)>>>(
        Wproj, wph, KDIM, CDIM);
    bias_build_kernel<<<(HEADS * NTOK * NTOK + 255) / 256, 256>>>(
        table, relix, bias_g);

    // 1) qkv = half(x @ W_qkv + b)   (M=200704, N=1152, K=384)
    gemm_f16_kernel<<<dim3(N_QKV / 128, MROWS / 128), 256, GEMM_SMEM>>>(
        xh, wqh, bqkv, qkvh, N_QKV, 1);

    // 2) attention (fp16 tensor-core), one block per (window, head-pair)
    attn_h_kernel<<<dim3(BTOT, HEADS / 2), 128>>>(qkvh, bias_g, ctxh);

    // 3) out = ctx @ W_proj + b      (M=200704, N=384, K=384), f32 out
    gemm_f16_kernel<<<dim3(CDIM / 128, MROWS / 128), 256, GEMM_SMEM>>>(
        ctxh, wph, bproj, out, CDIM, 0);
}